// round 11
// baseline (speedup 1.0000x reference)
#include <cuda_runtime.h>
#include <math.h>

// ---------------------------------------------------------------------------
// AddTaskModel SNN scan: S=1024, B=2048, D=2, H=128.
// Persistent batch-partitioned kernel: 128 CTAs x 256 threads, 16 batch/CTA.
// Each thread owns (1 hidden unit h, 8 batch elements).
//
// Exact-fp32 reference-matching round (tf32 falsified in R9):
//   - dots: ascending-K, single fp32 accumulator, FMA chain (cublas sgemm order)
//   - bias added AFTER each dot sum (XLA fuses bias as a separate add)
//   - sigmoid = 1 / (1 + expf(-x)) with IEEE divide (XLA logistic exp-form)
//   - elementwise state update in plain fp32 RN ops
//   - deterministic double-precision loss reduction
// States live in registers; shared memory holds fp32 copies as GEMM inputs.
// ---------------------------------------------------------------------------

#define H        128
#define BT       16          // batch per CTA
#define NCTA     128
#define NTHREADS 256
#define NSTEPS   1024
#define BTOT     2048

// Shared layout (floats)
#define OFF_WMD   0            // 16384  WtauM dense-half, [j][h]
#define OFF_WAD   16384        // 16384  WtauAdp dense-half, [j][h]
#define OFF_WMM   32768        // 16384  WtauM mem-half, [j][h]
#define OFF_DEN   49152        // 2048   dense[b][j]
#define OFF_MEM   51200        // 2048   mem
#define OFF_BB    53248        // 2048   bb
#define OFF_SPK   55296        // 2048   spk (0/1)
#define OFF_BTM   57344        // 128
#define OFF_BTA   57472        // 128
#define OFF_B1X   57600        // 128
#define OFF_W1XX  57728        // 256    W1x x-part, [d][h]
#define OFF_XT    57984        // 32     x_t; reused as double[16] for loss
#define SMEM_FLOATS 58016
#define SMEM_BYTES  (SMEM_FLOATS * 4)   // 232064 <= 232448 (227KB opt-in)

// __device__ scratch (static device globals are allowed)
__device__ float  gWmD[128 * 128];
__device__ float  gWaD[128 * 128];
__device__ float  gWmM[128 * 128];
__device__ float  gWaB[128 * 128];   // streamed: WtauAdp bb-half, [j][h]
__device__ float  gW1xS[128 * 128];  // streamed: W1x spk-part, [j][h]
__device__ float  gW1xX[2 * 128];    // W1x x-part, [d][h]
__device__ double gDloss;            // deterministic loss accumulator

__global__ void prep_kernel(const float* __restrict__ W1x,
                            const float* __restrict__ WtauM,
                            const float* __restrict__ WtauAdp)
{
    int j = blockIdx.x;      // 0..127
    int h = threadIdx.x;     // 0..127
    gWmD[j * 128 + h]  = WtauM[h * 256 + j];
    gWmM[j * 128 + h]  = WtauM[h * 256 + 128 + j];
    gWaD[j * 128 + h]  = WtauAdp[h * 256 + j];
    gWaB[j * 128 + h]  = WtauAdp[h * 256 + 128 + j];
    gW1xS[j * 128 + h] = W1x[h * 130 + 2 + j];
    if (j < 2) gW1xX[j * 128 + h] = W1x[h * 130 + j];
    if (j == 0 && h == 0) gDloss = 0.0;   // graph replays: re-zero every launch
}

__global__ void finalize_kernel(float* __restrict__ out)
{
    out[0] = (float)(gDloss * (1.0 / 2048.0));
}

// XLA logistic (exp form): sigmoid(x) = 1 / (1 + exp(-x)), libm expf, IEEE div
__device__ __forceinline__ float sigmoid_ref(float v)
{
    return 1.0f / (1.0f + expf(-v));
}

__global__ __launch_bounds__(NTHREADS, 1)
void snn_kernel(const float* __restrict__ x,      // [S,B,D]
                const float* __restrict__ y,      // [B]
                const float* __restrict__ h0m,
                const float* __restrict__ h0s,
                const float* __restrict__ h0b,
                const float* __restrict__ b1x,
                const float* __restrict__ btm,
                const float* __restrict__ bta,
                const float* __restrict__ Wlin,   // [H]
                const float* __restrict__ blin)   // [1]
{
    extern __shared__ float sm[];
    float* sWmD = sm + OFF_WMD;
    float* sWaD = sm + OFF_WAD;
    float* sWmM = sm + OFF_WMM;
    float* sDen = sm + OFF_DEN;
    float* sMem = sm + OFF_MEM;
    float* sBb  = sm + OFF_BB;
    float* sSpk = sm + OFF_SPK;
    float* sBtm = sm + OFF_BTM;
    float* sBta = sm + OFF_BTA;
    float* sB1x = sm + OFF_B1X;
    float* sW1xX = sm + OFF_W1XX;
    float* sXt  = sm + OFF_XT;

    const int tid    = threadIdx.x;
    const int batch0 = blockIdx.x * BT;

    const int w      = tid >> 5;
    const int lane   = tid & 31;
    const int hblock = (w & 3) * 32;
    const int h      = hblock + lane;
    const int bg     = (w >> 2) * 8;      // batch group base (0 or 8)

    // ---- one-time loads ----
    for (int i = tid; i < 16384; i += NTHREADS) {
        sWmD[i] = gWmD[i];
        sWaD[i] = gWaD[i];
        sWmM[i] = gWmM[i];
    }
    if (tid < 128) {
        sBtm[tid] = btm[tid];
        sBta[tid] = bta[tid];
        sB1x[tid] = b1x[tid];
    }
    sW1xX[tid] = gW1xX[tid];   // 256 values, 256 threads

    // ---- state in registers; shared holds copies used as GEMM inputs ----
    float mem_r[8], bb_r[8], spk_r[8];
    #pragma unroll
    for (int b = 0; b < 8; ++b) {
        const int gidx = (batch0 + bg + b) * H + h;
        const int idx  = (bg + b) * H + h;
        mem_r[b] = h0m[gidx];
        spk_r[b] = h0s[gidx];
        bb_r[b]  = h0b[gidx];
        sMem[idx] = mem_r[b];
        sSpk[idx] = spk_r[b];
        sBb[idx]  = bb_r[b];
    }
    __syncthreads();

    const float* gs = gW1xS + h;          // stride 128 per j
    const float* ga = gWaB + h;

    for (int t = 0; t < NSTEPS; ++t) {
        // stage x_t for this CTA's 16 batches (32 floats, contiguous)
        if (tid < 32) sXt[tid] = x[((size_t)t * BTOT + batch0) * 2 + tid];
        __syncthreads();   // also orders previous step's phase-3 shared writes

        // -------- phase 1: dense = [x_t, spk] @ W1x.T ; + b1x after --------
        // single fp32 accumulator, ascending K = [x0, x1, spk0..spk127]
        float d[8];
        const float w1x0 = sW1xX[h];
        const float w1x1 = sW1xX[128 + h];
        #pragma unroll
        for (int b = 0; b < 8; ++b) {
            const int bl = bg + b;
            d[b] = fmaf(w1x1, sXt[bl * 2 + 1], w1x0 * sXt[bl * 2]);
        }
        {
            float wn[8];
            #pragma unroll
            for (int k = 0; k < 8; ++k) wn[k] = __ldg(gs + k * 128);
            for (int j0 = 0; j0 < 128; j0 += 8) {
                float wc[8];
                #pragma unroll
                for (int k = 0; k < 8; ++k) wc[k] = wn[k];
                if (j0 + 8 < 128) {
                    #pragma unroll
                    for (int k = 0; k < 8; ++k) wn[k] = __ldg(gs + (j0 + 8 + k) * 128);
                }
                #pragma unroll
                for (int b = 0; b < 8; ++b) {
                    const float4 s0 = *(const float4*)(sSpk + (bg + b) * H + j0);
                    const float4 s1 = *(const float4*)(sSpk + (bg + b) * H + j0 + 4);
                    float a = d[b];
                    a = fmaf(s0.x, wc[0], a); a = fmaf(s0.y, wc[1], a);
                    a = fmaf(s0.z, wc[2], a); a = fmaf(s0.w, wc[3], a);
                    a = fmaf(s1.x, wc[4], a); a = fmaf(s1.y, wc[5], a);
                    a = fmaf(s1.z, wc[6], a); a = fmaf(s1.w, wc[7], a);
                    d[b] = a;
                }
            }
        }
        const float bias1 = sB1x[h];
        #pragma unroll
        for (int b = 0; b < 8; ++b) {
            d[b] = d[b] + bias1;                    // bias AFTER the sum
            sDen[(bg + b) * H + h] = d[b];
        }
        __syncthreads();

        // -------- phase 2: tau pre-activations (K=256, ascending) --------
        float accM[8], accA[8];
        #pragma unroll
        for (int b = 0; b < 8; ++b) { accM[b] = 0.0f; accA[b] = 0.0f; }

        // dense-input half (shared by both matrices), j = 0..127
        for (int j0 = 0; j0 < 128; j0 += 8) {
            float wm[8], wa[8];
            #pragma unroll
            for (int k = 0; k < 8; ++k) {
                wm[k] = sWmD[(j0 + k) * 128 + h];
                wa[k] = sWaD[(j0 + k) * 128 + h];
            }
            #pragma unroll
            for (int b = 0; b < 8; ++b) {
                const float4 d0 = *(const float4*)(sDen + (bg + b) * H + j0);
                const float4 d1 = *(const float4*)(sDen + (bg + b) * H + j0 + 4);
                float am = accM[b];
                am = fmaf(d0.x, wm[0], am); am = fmaf(d0.y, wm[1], am);
                am = fmaf(d0.z, wm[2], am); am = fmaf(d0.w, wm[3], am);
                am = fmaf(d1.x, wm[4], am); am = fmaf(d1.y, wm[5], am);
                am = fmaf(d1.z, wm[6], am); am = fmaf(d1.w, wm[7], am);
                accM[b] = am;
                float aa = accA[b];
                aa = fmaf(d0.x, wa[0], aa); aa = fmaf(d0.y, wa[1], aa);
                aa = fmaf(d0.z, wa[2], aa); aa = fmaf(d0.w, wa[3], aa);
                aa = fmaf(d1.x, wa[4], aa); aa = fmaf(d1.y, wa[5], aa);
                aa = fmaf(d1.z, wa[6], aa); aa = fmaf(d1.w, wa[7], aa);
                accA[b] = aa;
            }
        }
        // tauM mem-half, j = 128..255 (continues same accumulator, ascending)
        for (int j0 = 0; j0 < 128; j0 += 8) {
            float wm[8];
            #pragma unroll
            for (int k = 0; k < 8; ++k) wm[k] = sWmM[(j0 + k) * 128 + h];
            #pragma unroll
            for (int b = 0; b < 8; ++b) {
                const float4 m0 = *(const float4*)(sMem + (bg + b) * H + j0);
                const float4 m1 = *(const float4*)(sMem + (bg + b) * H + j0 + 4);
                float am = accM[b];
                am = fmaf(m0.x, wm[0], am); am = fmaf(m0.y, wm[1], am);
                am = fmaf(m0.z, wm[2], am); am = fmaf(m0.w, wm[3], am);
                am = fmaf(m1.x, wm[4], am); am = fmaf(m1.y, wm[5], am);
                am = fmaf(m1.z, wm[6], am); am = fmaf(m1.w, wm[7], am);
                accM[b] = am;
            }
        }
        // tauA bb-half, j = 128..255 (streamed weights, 8-deep prefetch)
        {
            float wn[8];
            #pragma unroll
            for (int k = 0; k < 8; ++k) wn[k] = __ldg(ga + k * 128);
            for (int j0 = 0; j0 < 128; j0 += 8) {
                float wc[8];
                #pragma unroll
                for (int k = 0; k < 8; ++k) wc[k] = wn[k];
                if (j0 + 8 < 128) {
                    #pragma unroll
                    for (int k = 0; k < 8; ++k) wn[k] = __ldg(ga + (j0 + 8 + k) * 128);
                }
                #pragma unroll
                for (int b = 0; b < 8; ++b) {
                    const float4 s0 = *(const float4*)(sBb + (bg + b) * H + j0);
                    const float4 s1 = *(const float4*)(sBb + (bg + b) * H + j0 + 4);
                    float aa = accA[b];
                    aa = fmaf(s0.x, wc[0], aa); aa = fmaf(s0.y, wc[1], aa);
                    aa = fmaf(s0.z, wc[2], aa); aa = fmaf(s0.w, wc[3], aa);
                    aa = fmaf(s1.x, wc[4], aa); aa = fmaf(s1.y, wc[5], aa);
                    aa = fmaf(s1.z, wc[6], aa); aa = fmaf(s1.w, wc[7], aa);
                    accA[b] = aa;
                }
            }
        }
        __syncthreads();   // everyone done READING old state copies

        // -------- phase 3: elementwise state update (plain fp32, RN) --------
        const float bm = sBtm[h], ba = sBta[h];
        #pragma unroll
        for (int b = 0; b < 8; ++b) {
            const int idx = (bg + b) * H + h;
            const float tm = sigmoid_ref(accM[b] + bm);
            const float ta = sigmoid_ref(accA[b] + ba);
            const float spo = spk_r[b];
            const float bn  = ta * bb_r[b] + (1.0f - ta) * spo;
            const float Bth = 0.01f + 1.8f * bn;
            const float mn  = mem_r[b] * tm + (1.0f - tm) * d[b] - Bth * spo;
            const float sn  = (mn - Bth > 0.0f) ? 1.0f : 0.0f;
            bb_r[b]  = bn;
            mem_r[b] = mn;
            spk_r[b] = sn;
            sBb[idx]  = bn;
            sMem[idx] = mn;
            sSpk[idx] = sn;
        }
    }
    __syncthreads();

    // -------- readout: out[b] = mem[b] @ Wlin + blin -------
    double* sD = (double*)sXt;   // 16 doubles, 8B aligned
    #pragma unroll
    for (int r = 0; r < 2; ++r) {
        const int bl = w * 2 + r;
        double p = 0.0;
        #pragma unroll
        for (int o = 0; o < 4; ++o) {
            const int hh = lane + 32 * o;
            p += (double)sMem[bl * H + hh] * (double)Wlin[hh];
        }
        #pragma unroll
        for (int off = 16; off; off >>= 1) p += __shfl_xor_sync(0xFFFFFFFFu, p, off);
        if (lane == 0) {
            const double o  = p + (double)blin[0];
            const double df = o - (double)y[batch0 + bl];
            sD[bl] = df * df;
        }
    }
    __syncthreads();
    if (tid == 0) {
        double s = 0.0;
        #pragma unroll
        for (int i = 0; i < BT; ++i) s += sD[i];
        atomicAdd(&gDloss, s);
    }
}

extern "C" void kernel_launch(void* const* d_in, const int* in_sizes, int n_in,
                              void* d_out, int out_size)
{
    const float* x       = (const float*)d_in[0];
    const float* y       = (const float*)d_in[1];
    const float* h0_mem  = (const float*)d_in[2];
    const float* h0_spk  = (const float*)d_in[3];
    const float* h0_b    = (const float*)d_in[4];
    const float* W1x     = (const float*)d_in[5];
    const float* b1x     = (const float*)d_in[6];
    const float* WtauM   = (const float*)d_in[7];
    const float* btauM   = (const float*)d_in[8];
    const float* WtauAdp = (const float*)d_in[9];
    const float* btauAdp = (const float*)d_in[10];
    const float* Wlin    = (const float*)d_in[11];
    const float* blin    = (const float*)d_in[12];
    float* out = (float*)d_out;

    cudaFuncSetAttribute(snn_kernel, cudaFuncAttributeMaxDynamicSharedMemorySize,
                         SMEM_BYTES);

    prep_kernel<<<128, 128>>>(W1x, WtauM, WtauAdp);
    snn_kernel<<<NCTA, NTHREADS, SMEM_BYTES>>>(x, y, h0_mem, h0_spk, h0_b,
                                               b1x, btauM, btauAdp,
                                               Wlin, blin);
    finalize_kernel<<<1, 1>>>(out);
}